// round 12
// baseline (speedup 1.0000x reference)
#include <cuda_runtime.h>
#include <cuda_bf16.h>
#include <cstdint>

#define N_NODES 100000
#define D_FEAT 128
#define K_NEIGH 16

// ---------------------------------------------------------------------------
// Device scratch (no allocations) — same footprint as the verified R1 kernel.
// ---------------------------------------------------------------------------
__device__ float g_h[(size_t)N_NODES * D_FEAT];     // layer-0 output (post-relu)
__device__ float g_agg[(size_t)N_NODES * D_FEAT];   // gathered neighbor means

// ---------------------------------------------------------------------------
// mma.sync m16n8k16 bf16 (arch-neutral PTX, sm_80-era; valid on compute_103)
// ---------------------------------------------------------------------------
__device__ __forceinline__ void mma_bf16(float* c, const uint32_t* a, const uint32_t* b) {
    asm volatile("mma.sync.aligned.m16n8k16.row.col.f32.bf16.bf16.f32 "
                 "{%0,%1,%2,%3}, {%4,%5,%6,%7}, {%8,%9}, {%0,%1,%2,%3};"
                 : "+f"(c[0]), "+f"(c[1]), "+f"(c[2]), "+f"(c[3])
                 : "r"(a[0]), "r"(a[1]), "r"(a[2]), "r"(a[3]), "r"(b[0]), "r"(b[1]));
}
__device__ __forceinline__ uint32_t lds32(const __nv_bfloat16* p) {
    return *reinterpret_cast<const uint32_t*>(p);
}

// ---------------------------------------------------------------------------
// Gather + mean (VERBATIM from the R1 kernel that passed): one warp per node.
// ---------------------------------------------------------------------------
__global__ void gather_mean_kernel(const float* __restrict__ h,
                                   const int* __restrict__ idx) {
    int gwarp = (blockIdx.x * blockDim.x + threadIdx.x) >> 5;
    int lane = threadIdx.x & 31;
    if (gwarp >= N_NODES) return;

    const int* ip = idx + (size_t)gwarp * K_NEIGH;
    int myidx = (lane < K_NEIGH) ? ip[lane] : 0;

    int c = lane * 4;
    float4 s = make_float4(0.f, 0.f, 0.f, 0.f);
#pragma unroll
    for (int k = 0; k < K_NEIGH; ++k) {
        int r = __shfl_sync(0xffffffffu, myidx, k);
        float4 v = *reinterpret_cast<const float4*>(h + (size_t)r * D_FEAT + c);
        s.x += v.x; s.y += v.y; s.z += v.z; s.w += v.w;
    }
    const float inv = 1.0f / (float)K_NEIGH;
    s.x *= inv; s.y *= inv; s.z *= inv; s.w *= inv;
    *reinterpret_cast<float4*>(g_agg + (size_t)gwarp * D_FEAT + c) = s;
}

// ---------------------------------------------------------------------------
// Fused GEMM: D[128 x 128] = [self | agg](128 x 256) @ W[256 x 128] + b.
// fp32 sources split on the fly into bf16 hi/lo smem tiles; split-precision
// 3-MMA (hi*hi + hi*lo + lo*hi) into fp32 accumulators; fragments loaded with
// plain LDS.32 per the documented PTX mma.m16n8k16 thread mappings.
// ---------------------------------------------------------------------------
#define BM 128
#define BN 128
#define BK 32
#define ASTRIDE 40   // bf16 elems per smem row: 80B, 16B-aligned, conflict-free

__global__ void __launch_bounds__(256)
sage_gemm_mma(const float* __restrict__ selfF,   // [N,128] fp32 (feats or g_h)
              const float* __restrict__ Wl,      // [256,128] fp32, layer offset applied
              const float* __restrict__ bias,    // [128]
              float* __restrict__ outF,          // g_h (layer0) or d_out (layer1)
              int layer) {
    __shared__ __align__(16) __nv_bfloat16 sAh[BM][ASTRIDE];
    __shared__ __align__(16) __nv_bfloat16 sAl[BM][ASTRIDE];
    __shared__ __align__(16) __nv_bfloat16 sBh[BN][ASTRIDE];
    __shared__ __align__(16) __nv_bfloat16 sBl[BN][ASTRIDE];

    const int tid = threadIdx.x;
    const int wid = tid >> 5;
    const int lane = tid & 31;
    const int gid = lane >> 2;     // groupID 0..7
    const int tig = lane & 3;      // threadID-in-group 0..3
    const int row0 = blockIdx.x * BM;
    const int mbase = (wid & 3) * 32;   // warp covers 32 M-rows (2 m16 tiles)
    const int ncol = (wid >> 2) * 64;   // warp covers 64 N-cols (8 n8 tiles)

    float acc[2][8][4];
#pragma unroll
    for (int mt = 0; mt < 2; ++mt)
#pragma unroll
        for (int t = 0; t < 8; ++t)
#pragma unroll
            for (int j = 0; j < 4; ++j) acc[mt][t][j] = 0.f;

#pragma unroll 1
    for (int c = 0; c < 8; ++c) {
        const float* __restrict__ srcA = (c < 4) ? selfF : g_agg;
        const int kb = (c & 3) * BK;   // k-offset within the 128-wide source
        const int kw = c * BK;         // k-offset within W's 256 rows

        // ---- A: 128 rows x 32 k fp32 -> split to sAh/sAl (1024 float4) ----
#pragma unroll
        for (int it = 0; it < 4; ++it) {
            int u = tid + it * 256;    // 0..1023
            int r = u >> 3;            // 0..127
            int q = u & 7;             // 0..7 (4 k each)
            int g = row0 + r;
            float4 v = make_float4(0.f, 0.f, 0.f, 0.f);
            if (g < N_NODES)
                v = *reinterpret_cast<const float4*>(srcA + (size_t)g * 128 + kb + q * 4);
            __align__(8) __nv_bfloat16 hb[4], lb[4];
            hb[0] = __float2bfloat16(v.x); lb[0] = __float2bfloat16(v.x - __bfloat162float(hb[0]));
            hb[1] = __float2bfloat16(v.y); lb[1] = __float2bfloat16(v.y - __bfloat162float(hb[1]));
            hb[2] = __float2bfloat16(v.z); lb[2] = __float2bfloat16(v.z - __bfloat162float(hb[2]));
            hb[3] = __float2bfloat16(v.w); lb[3] = __float2bfloat16(v.w - __bfloat162float(hb[3]));
            *reinterpret_cast<uint2*>(&sAh[r][q * 4]) = *reinterpret_cast<uint2*>(hb);
            *reinterpret_cast<uint2*>(&sAl[r][q * 4]) = *reinterpret_cast<uint2*>(lb);
        }

        // ---- B: W[kw..kw+32)[0..128) fp32 -> split to sBh/sBl (transposed) --
        {
            int n = tid & 127;         // output column
            int khalf = tid >> 7;      // 0 or 1: which 16 k's
            int kbase = kw + khalf * 16;
            float w[16];
#pragma unroll
            for (int i = 0; i < 16; ++i)
                w[i] = Wl[(size_t)(kbase + i) * 128 + n];   // coalesced across lanes
            __align__(16) __nv_bfloat16 hb[16], lb[16];
#pragma unroll
            for (int i = 0; i < 16; ++i) {
                hb[i] = __float2bfloat16(w[i]);
                lb[i] = __float2bfloat16(w[i] - __bfloat162float(hb[i]));
            }
            *reinterpret_cast<uint4*>(&sBh[n][khalf * 16])     = *reinterpret_cast<uint4*>(hb);
            *reinterpret_cast<uint4*>(&sBh[n][khalf * 16 + 8]) = *reinterpret_cast<uint4*>(hb + 8);
            *reinterpret_cast<uint4*>(&sBl[n][khalf * 16])     = *reinterpret_cast<uint4*>(lb);
            *reinterpret_cast<uint4*>(&sBl[n][khalf * 16 + 8]) = *reinterpret_cast<uint4*>(lb + 8);
        }
        __syncthreads();

        // ---- compute: 2 k-steps of 16; fragments via documented mappings ----
#pragma unroll
        for (int kk = 0; kk < BK; kk += 16) {
            uint32_t ah[2][4], al[2][4];
#pragma unroll
            for (int mt = 0; mt < 2; ++mt) {
                int ar = mbase + mt * 16;
                ah[mt][0] = lds32(&sAh[ar + gid    ][kk + 2 * tig    ]);
                ah[mt][1] = lds32(&sAh[ar + gid + 8][kk + 2 * tig    ]);
                ah[mt][2] = lds32(&sAh[ar + gid    ][kk + 2 * tig + 8]);
                ah[mt][3] = lds32(&sAh[ar + gid + 8][kk + 2 * tig + 8]);
                al[mt][0] = lds32(&sAl[ar + gid    ][kk + 2 * tig    ]);
                al[mt][1] = lds32(&sAl[ar + gid + 8][kk + 2 * tig    ]);
                al[mt][2] = lds32(&sAl[ar + gid    ][kk + 2 * tig + 8]);
                al[mt][3] = lds32(&sAl[ar + gid + 8][kk + 2 * tig + 8]);
            }
            uint32_t bh[8][2], bl[8][2];
#pragma unroll
            for (int t = 0; t < 8; ++t) {
                int nb = ncol + t * 8;
                bh[t][0] = lds32(&sBh[nb + gid][kk + 2 * tig    ]);
                bh[t][1] = lds32(&sBh[nb + gid][kk + 2 * tig + 8]);
                bl[t][0] = lds32(&sBl[nb + gid][kk + 2 * tig    ]);
                bl[t][1] = lds32(&sBl[nb + gid][kk + 2 * tig + 8]);
            }
#pragma unroll
            for (int mt = 0; mt < 2; ++mt)
#pragma unroll
                for (int t = 0; t < 8; ++t) {
                    mma_bf16(acc[mt][t], ah[mt], bh[t]);   // hi * hi
                    mma_bf16(acc[mt][t], ah[mt], bl[t]);   // hi * lo
                    mma_bf16(acc[mt][t], al[mt], bh[t]);   // lo * hi
                }
        }
        __syncthreads();
    }

    // ---- epilogue: bias (+ReLU for layer 0), float2 stores ----
#pragma unroll
    for (int mt = 0; mt < 2; ++mt)
#pragma unroll
        for (int t = 0; t < 8; ++t) {
            int col = ncol + t * 8 + tig * 2;
            float b0 = __ldg(bias + col);
            float b1 = __ldg(bias + col + 1);
#pragma unroll
            for (int hr = 0; hr < 2; ++hr) {
                int g = row0 + mbase + mt * 16 + hr * 8 + gid;
                if (g < N_NODES) {
                    float z0 = acc[mt][t][2 * hr + 0] + b0;
                    float z1 = acc[mt][t][2 * hr + 1] + b1;
                    if (layer == 0) {
                        z0 = fmaxf(z0, 0.f);
                        z1 = fmaxf(z1, 0.f);
                    }
                    *reinterpret_cast<float2*>(outF + (size_t)g * 128 + col) =
                        make_float2(z0, z1);
                }
            }
        }
}

// ---------------------------------------------------------------------------
// Launch: gather -> gemm -> gather -> gemm. Graph-capturable, allocation-free.
// ---------------------------------------------------------------------------
extern "C" void kernel_launch(void* const* d_in, const int* in_sizes, int n_in,
                              void* d_out, int out_size) {
    const float* feats = (const float*)d_in[0];
    const int*   nidx  = (const int*)d_in[1];
    const float* Ws    = (const float*)d_in[2];
    const float* bs    = (const float*)d_in[3];
    float* out = (float*)d_out;

    const int gather_blocks = (N_NODES * 32 + 255) / 256;   // 12500
    const int gemm_blocks = (N_NODES + BM - 1) / BM;        // 782

    // Layer 0: agg = mean(feats[idx0]); g_h = relu([feats|agg] @ W0 + b0)
    gather_mean_kernel<<<gather_blocks, 256>>>(feats, nidx);
    sage_gemm_mma<<<gemm_blocks, 256>>>(feats, Ws, bs, g_h, 0);

    // Layer 1: agg = mean(g_h[idx1]); out = [g_h|agg] @ W1 + b1
    gather_mean_kernel<<<gather_blocks, 256>>>(g_h, nidx + (size_t)N_NODES * K_NEIGH);
    sage_gemm_mma<<<gemm_blocks, 256>>>(g_h, Ws + 256 * 128, bs + 128, out, 1);
}

// round 15
// speedup vs baseline: 1.0253x; 1.0253x over previous
#include <cuda_runtime.h>
#include <cuda_bf16.h>
#include <cstdint>

#define N_NODES 100000
#define D_FEAT 128
#define K_NEIGH 16

// ---------------------------------------------------------------------------
// Device scratch (no allocations).
// ---------------------------------------------------------------------------
__device__ float g_h[(size_t)N_NODES * D_FEAT];     // layer-0 output (post-relu)
__device__ float g_agg[(size_t)N_NODES * D_FEAT];   // gathered neighbor means

// ---------------------------------------------------------------------------
// mma.sync m16n8k16 bf16 (arch-neutral PTX; HW-verified correct in R12)
// ---------------------------------------------------------------------------
__device__ __forceinline__ void mma_bf16(float* c, const uint32_t* a, const uint32_t* b) {
    asm volatile("mma.sync.aligned.m16n8k16.row.col.f32.bf16.bf16.f32 "
                 "{%0,%1,%2,%3}, {%4,%5,%6,%7}, {%8,%9}, {%0,%1,%2,%3};"
                 : "+f"(c[0]), "+f"(c[1]), "+f"(c[2]), "+f"(c[3])
                 : "r"(a[0]), "r"(a[1]), "r"(a[2]), "r"(a[3]), "r"(b[0]), "r"(b[1]));
}
__device__ __forceinline__ uint32_t lds32(const __nv_bfloat16* p) {
    return *reinterpret_cast<const uint32_t*>(p);
}

// ---------------------------------------------------------------------------
// Gather + mean (verbatim, HW-verified): one warp per node.
// ---------------------------------------------------------------------------
__global__ void gather_mean_kernel(const float* __restrict__ h,
                                   const int* __restrict__ idx) {
    int gwarp = (blockIdx.x * blockDim.x + threadIdx.x) >> 5;
    int lane = threadIdx.x & 31;
    if (gwarp >= N_NODES) return;

    const int* ip = idx + (size_t)gwarp * K_NEIGH;
    int myidx = (lane < K_NEIGH) ? ip[lane] : 0;

    int c = lane * 4;
    float4 s = make_float4(0.f, 0.f, 0.f, 0.f);
#pragma unroll
    for (int k = 0; k < K_NEIGH; ++k) {
        int r = __shfl_sync(0xffffffffu, myidx, k);
        float4 v = *reinterpret_cast<const float4*>(h + (size_t)r * D_FEAT + c);
        s.x += v.x; s.y += v.y; s.z += v.z; s.w += v.w;
    }
    const float inv = 1.0f / (float)K_NEIGH;
    s.x *= inv; s.y *= inv; s.z *= inv; s.w *= inv;
    *reinterpret_cast<float4*>(g_agg + (size_t)gwarp * D_FEAT + c) = s;
}

// ---------------------------------------------------------------------------
// Pipelined GEMM: D[64 x 128] = [self | agg](64 x 256) @ W[256 x 128] + b.
// Same proven split-bf16 3-MMA core; register prefetch of chunk c+1's
// A/B global data while chunk c computes, hiding LDG latency behind MMAs.
// Single-buffered smem (30 KB static), BM=64, 2 CTAs/SM.
// ---------------------------------------------------------------------------
#define BM 64
#define BN 128
#define BK 32
#define ASTRIDE 40   // bf16 elems per smem row: 80B, 16B-aligned, conflict-free reads

__global__ void __launch_bounds__(256, 2)
sage_gemm_mma(const float* __restrict__ selfF,   // [N,128] fp32 (feats or g_h)
              const float* __restrict__ Wl,      // [256,128] fp32 (layer slice)
              const float* __restrict__ bias,    // [128]
              float* __restrict__ outF,          // g_h (layer0) or d_out (layer1)
              int layer) {
    __shared__ __align__(16) __nv_bfloat16 sAh[BM][ASTRIDE];   //  5 KB
    __shared__ __align__(16) __nv_bfloat16 sAl[BM][ASTRIDE];   //  5 KB
    __shared__ __align__(16) __nv_bfloat16 sBh[BN][ASTRIDE];   // 10 KB
    __shared__ __align__(16) __nv_bfloat16 sBl[BN][ASTRIDE];   // 10 KB

    const int tid = threadIdx.x;
    const int wid = tid >> 5;
    const int lane = tid & 31;
    const int gid = lane >> 2;     // groupID 0..7
    const int tig = lane & 3;      // threadID-in-group 0..3
    const int row0 = blockIdx.x * BM;
    const int mrow = (wid & 3) * 16;    // warp's m16 tile
    const int ncol = (wid >> 2) * 64;   // warp's 64-col half

    // A-loader decomposition (2 float4 per thread per chunk)
    const int ar0 = tid >> 3,          aq0 = tid & 7;          // u = tid
    const int ar1 = (tid + 256) >> 3,  aq1 = (tid + 256) & 7;  // u = tid+256
    // B-loader decomposition (16 floats per thread per chunk)
    const int bn = tid & 127;
    const int bkh = tid >> 7;

    float acc[8][4];
#pragma unroll
    for (int t = 0; t < 8; ++t)
#pragma unroll
        for (int j = 0; j < 4; ++j) acc[t][j] = 0.f;

    // ---- prefetch chunk 0 into registers ----
    float4 av[2];
    float wv[16];
    {
        const float* __restrict__ srcA = selfF;
        int g0 = row0 + ar0, g1 = row0 + ar1;
        av[0] = (g0 < N_NODES) ? *reinterpret_cast<const float4*>(srcA + (size_t)g0 * 128 + aq0 * 4)
                               : make_float4(0.f, 0.f, 0.f, 0.f);
        av[1] = (g1 < N_NODES) ? *reinterpret_cast<const float4*>(srcA + (size_t)g1 * 128 + aq1 * 4)
                               : make_float4(0.f, 0.f, 0.f, 0.f);
        int kbase = bkh * 16;
#pragma unroll
        for (int i = 0; i < 16; ++i)
            wv[i] = Wl[(size_t)(kbase + i) * 128 + bn];
    }

#pragma unroll 1
    for (int c = 0; c < 8; ++c) {
        // ---- convert + STS chunk c from registers ----
        {
            const int rr[2] = {ar0, ar1};
            const int qq[2] = {aq0, aq1};
#pragma unroll
            for (int j = 0; j < 2; ++j) {
                float4 v = av[j];
                __align__(8) __nv_bfloat16 hb[4], lb[4];
                hb[0] = __float2bfloat16(v.x); lb[0] = __float2bfloat16(v.x - __bfloat162float(hb[0]));
                hb[1] = __float2bfloat16(v.y); lb[1] = __float2bfloat16(v.y - __bfloat162float(hb[1]));
                hb[2] = __float2bfloat16(v.z); lb[2] = __float2bfloat16(v.z - __bfloat162float(hb[2]));
                hb[3] = __float2bfloat16(v.w); lb[3] = __float2bfloat16(v.w - __bfloat162float(hb[3]));
                *reinterpret_cast<uint2*>(&sAh[rr[j]][qq[j] * 4]) = *reinterpret_cast<uint2*>(hb);
                *reinterpret_cast<uint2*>(&sAl[rr[j]][qq[j] * 4]) = *reinterpret_cast<uint2*>(lb);
            }
            __align__(16) __nv_bfloat16 hb[16], lb[16];
#pragma unroll
            for (int i = 0; i < 16; ++i) {
                hb[i] = __float2bfloat16(wv[i]);
                lb[i] = __float2bfloat16(wv[i] - __bfloat162float(hb[i]));
            }
            *reinterpret_cast<uint4*>(&sBh[bn][bkh * 16])     = *reinterpret_cast<uint4*>(hb);
            *reinterpret_cast<uint4*>(&sBh[bn][bkh * 16 + 8]) = *reinterpret_cast<uint4*>(hb + 8);
            *reinterpret_cast<uint4*>(&sBl[bn][bkh * 16])     = *reinterpret_cast<uint4*>(lb);
            *reinterpret_cast<uint4*>(&sBl[bn][bkh * 16 + 8]) = *reinterpret_cast<uint4*>(lb + 8);
        }
        __syncthreads();

        // ---- issue prefetch of chunk c+1 (overlaps with compute below) ----
        if (c < 7) {
            int cn = c + 1;
            const float* __restrict__ srcA = (cn < 4) ? selfF : g_agg;
            const int kb = (cn & 3) * BK;
            int g0 = row0 + ar0, g1 = row0 + ar1;
            av[0] = (g0 < N_NODES) ? *reinterpret_cast<const float4*>(srcA + (size_t)g0 * 128 + kb + aq0 * 4)
                                   : make_float4(0.f, 0.f, 0.f, 0.f);
            av[1] = (g1 < N_NODES) ? *reinterpret_cast<const float4*>(srcA + (size_t)g1 * 128 + kb + aq1 * 4)
                                   : make_float4(0.f, 0.f, 0.f, 0.f);
            int kbase = cn * BK + bkh * 16;
#pragma unroll
            for (int i = 0; i < 16; ++i)
                wv[i] = Wl[(size_t)(kbase + i) * 128 + bn];
        }

        // ---- compute chunk c (proven fragment mappings, verbatim) ----
#pragma unroll
        for (int kk = 0; kk < BK; kk += 16) {
            uint32_t ah[4], al[4];
            ah[0] = lds32(&sAh[mrow + gid    ][kk + 2 * tig    ]);
            ah[1] = lds32(&sAh[mrow + gid + 8][kk + 2 * tig    ]);
            ah[2] = lds32(&sAh[mrow + gid    ][kk + 2 * tig + 8]);
            ah[3] = lds32(&sAh[mrow + gid + 8][kk + 2 * tig + 8]);
            al[0] = lds32(&sAl[mrow + gid    ][kk + 2 * tig    ]);
            al[1] = lds32(&sAl[mrow + gid + 8][kk + 2 * tig    ]);
            al[2] = lds32(&sAl[mrow + gid    ][kk + 2 * tig + 8]);
            al[3] = lds32(&sAl[mrow + gid + 8][kk + 2 * tig + 8]);

            uint32_t bh[8][2], bl[8][2];
#pragma unroll
            for (int t = 0; t < 8; ++t) {
                int nb = ncol + t * 8;
                bh[t][0] = lds32(&sBh[nb + gid][kk + 2 * tig    ]);
                bh[t][1] = lds32(&sBh[nb + gid][kk + 2 * tig + 8]);
                bl[t][0] = lds32(&sBl[nb + gid][kk + 2 * tig    ]);
                bl[t][1] = lds32(&sBl[nb + gid][kk + 2 * tig + 8]);
            }
#pragma unroll
            for (int t = 0; t < 8; ++t) {
                mma_bf16(acc[t], ah, bh[t]);   // hi * hi
                mma_bf16(acc[t], ah, bl[t]);   // hi * lo
                mma_bf16(acc[t], al, bh[t]);   // lo * hi
            }
        }
        __syncthreads();
    }

    // ---- epilogue: bias (+ReLU for layer 0), float2 stores ----
#pragma unroll
    for (int t = 0; t < 8; ++t) {
        int col = ncol + t * 8 + tig * 2;
        float b0 = __ldg(bias + col);
        float b1 = __ldg(bias + col + 1);
#pragma unroll
        for (int hr = 0; hr < 2; ++hr) {
            int g = row0 + mrow + hr * 8 + gid;
            if (g < N_NODES) {
                float z0 = acc[t][2 * hr + 0] + b0;
                float z1 = acc[t][2 * hr + 1] + b1;
                if (layer == 0) {
                    z0 = fmaxf(z0, 0.f);
                    z1 = fmaxf(z1, 0.f);
                }
                *reinterpret_cast<float2*>(outF + (size_t)g * 128 + col) =
                    make_float2(z0, z1);
            }
        }
    }
}

// ---------------------------------------------------------------------------
// Launch: gather -> gemm -> gather -> gemm. Graph-capturable, allocation-free.
// ---------------------------------------------------------------------------
extern "C" void kernel_launch(void* const* d_in, const int* in_sizes, int n_in,
                              void* d_out, int out_size) {
    const float* feats = (const float*)d_in[0];
    const int*   nidx  = (const int*)d_in[1];
    const float* Ws    = (const float*)d_in[2];
    const float* bs    = (const float*)d_in[3];
    float* out = (float*)d_out;

    const int gather_blocks = (N_NODES * 32 + 255) / 256;   // 12500
    const int gemm_blocks = (N_NODES + BM - 1) / BM;        // 1563

    // Layer 0: agg = mean(feats[idx0]); g_h = relu([feats|agg] @ W0 + b0)
    gather_mean_kernel<<<gather_blocks, 256>>>(feats, nidx);
    sage_gemm_mma<<<gemm_blocks, 256>>>(feats, Ws, bs, g_h, 0);

    // Layer 1: agg = mean(g_h[idx1]); out = [g_h|agg] @ W1 + b1
    gather_mean_kernel<<<gather_blocks, 256>>>(g_h, nidx + (size_t)N_NODES * K_NEIGH);
    sage_gemm_mma<<<gemm_blocks, 256>>>(g_h, Ws + 256 * 128, bs + 128, out, 1);
}

// round 16
// speedup vs baseline: 1.0507x; 1.0248x over previous
#include <cuda_runtime.h>
#include <cuda_bf16.h>
#include <cstdint>

#define N_NODES 100000
#define D_FEAT 128
#define K_NEIGH 16

// ---------------------------------------------------------------------------
// Device scratch (no allocations) — same as the trusted R1 kernel.
// ---------------------------------------------------------------------------
__device__ float g_h[(size_t)N_NODES * D_FEAT];     // layer-0 output (post-relu)
__device__ float g_agg[(size_t)N_NODES * D_FEAT];   // gathered neighbor means

// ---------------------------------------------------------------------------
// cp.async helpers (sm_80-era PTX; valid on compute_103)
// ---------------------------------------------------------------------------
__device__ __forceinline__ uint32_t smem_u32(const void* p) {
    uint32_t a;
    asm("{ .reg .u64 t; cvta.to.shared.u64 t, %1; cvt.u32.u64 %0, t; }" : "=r"(a) : "l"(p));
    return a;
}
__device__ __forceinline__ void cpa16(uint32_t dst, const void* src, int nbytes) {
    asm volatile("cp.async.cg.shared.global [%0], [%1], 16, %2;"
                 :: "r"(dst), "l"(src), "r"(nbytes));
}
__device__ __forceinline__ void cpa8(uint32_t dst, const void* src, int nbytes) {
    asm volatile("cp.async.ca.shared.global [%0], [%1], 8, %2;"
                 :: "r"(dst), "l"(src), "r"(nbytes));
}
__device__ __forceinline__ void cpa_commit() {
    asm volatile("cp.async.commit_group;" ::: "memory");
}
template <int N>
__device__ __forceinline__ void cpa_wait() {
    asm volatile("cp.async.wait_group %0;" :: "n"(N) : "memory");
}

// ---------------------------------------------------------------------------
// Gather + mean (VERBATIM from R1, trusted): one warp per node.
// ---------------------------------------------------------------------------
__global__ void gather_mean_kernel(const float* __restrict__ h,
                                   const int* __restrict__ idx) {
    int gwarp = (blockIdx.x * blockDim.x + threadIdx.x) >> 5;
    int lane = threadIdx.x & 31;
    if (gwarp >= N_NODES) return;

    const int* ip = idx + (size_t)gwarp * K_NEIGH;
    int myidx = (lane < K_NEIGH) ? ip[lane] : 0;

    int c = lane * 4;
    float4 s = make_float4(0.f, 0.f, 0.f, 0.f);
#pragma unroll
    for (int k = 0; k < K_NEIGH; ++k) {
        int r = __shfl_sync(0xffffffffu, myidx, k);
        float4 v = *reinterpret_cast<const float4*>(h + (size_t)r * D_FEAT + c);
        s.x += v.x; s.y += v.y; s.z += v.z; s.w += v.w;
    }
    const float inv = 1.0f / (float)K_NEIGH;
    s.x *= inv; s.y *= inv; s.z *= inv; s.w *= inv;
    *reinterpret_cast<float4*>(g_agg + (size_t)gwarp * D_FEAT + c) = s;
}

// ---------------------------------------------------------------------------
// FFMA SAGE GEMM (R1 structure, trusted at 177us) + cp.async double buffering.
// z = [h | agg] @ W + b, optional ReLU. M=100000, N=128, K=256 in 16 chunks
// of BK=16. 256 threads, 8x8 microtile per thread (verbatim R1 compute).
// A smem is row-major [m][k] with ASTR=18 padding:
//   - cp.async 8B chunks land aligned ((18m+2q)*4 % 8 == 0)
//   - fragment reads a[i]=sA[ty*8+i][kk]: two addresses per warp, banks differ
//     by 8*18 = 144 = 16 (mod 32) -> conflict-free broadcast pair.
// B smem [k][n] rows of 128 floats: identical to R1; cp.async 16B chunks.
// ---------------------------------------------------------------------------
#define BM 128
#define BN 128
#define BK 16
#define ASTR 18

__global__ void __launch_bounds__(256, 2)
sage_gemm_ffma(const float* __restrict__ selfF,  // [N,128] (feats or g_h)
               const float* __restrict__ Wl,     // [256,128] layer slice
               const float* __restrict__ bias,   // [128]
               float* __restrict__ outF,         // g_h (layer0) or d_out
               int layer) {
    __shared__ float sA[2][BM][ASTR];   // 18.4 KB
    __shared__ float sB[2][BK][BN];     // 16.4 KB

    const int tid = threadIdx.x;
    const int tx = tid & 15;       // col group 0..15
    const int ty = tid >> 4;       // row group 0..15
    const int row0 = blockIdx.x * BM;

    float acc[8][8];
#pragma unroll
    for (int i = 0; i < 8; ++i)
#pragma unroll
        for (int j = 0; j < 8; ++j) acc[i][j] = 0.f;

    // Per-thread loader decompositions (constant across chunks):
    // A: 1024 8B-chunks -> 4/thread: r = u>>3 (row), q2 = u&7 (2 floats each)
    // B: 512 16B-chunks -> 2/thread: kk = u>>5, nq = (u&31)*4
    int a_r[4], a_q[4];
#pragma unroll
    for (int it = 0; it < 4; ++it) {
        int u = tid + it * 256;
        a_r[it] = u >> 3;
        a_q[it] = u & 7;
    }
    int b_k[2], b_n[2];
#pragma unroll
    for (int it = 0; it < 2; ++it) {
        int u = tid + it * 256;
        b_k[it] = u >> 5;
        b_n[it] = (u & 31) * 4;
    }

    // ---- chunk loader: issue cp.async for chunk c into buffer bf ----
    auto load_chunk = [&](int c, int bf) {
        const float* __restrict__ srcA = (c < 8) ? selfF : g_agg;
        const int kb = (c & 7) * BK;       // k-offset within 128-wide source
        const int kw = c * BK;             // k-offset within W's 256 rows
#pragma unroll
        for (int it = 0; it < 4; ++it) {
            int g = row0 + a_r[it];
            int ok = (g < N_NODES) ? 8 : 0;
            size_t gg = (g < N_NODES) ? (size_t)g : (size_t)(N_NODES - 1);
            cpa8(smem_u32(&sA[bf][a_r[it]][a_q[it] * 2]),
                 srcA + gg * 128 + kb + a_q[it] * 2, ok);
        }
#pragma unroll
        for (int it = 0; it < 2; ++it) {
            cpa16(smem_u32(&sB[bf][b_k[it]][b_n[it]]),
                  Wl + (size_t)(kw + b_k[it]) * 128 + b_n[it], 16);
        }
    };

    // ---- prologue: chunk 0 ----
    load_chunk(0, 0);
    cpa_commit();

#pragma unroll 1
    for (int c = 0; c < 16; ++c) {
        const int bf = c & 1;
        if (c < 15) {
            load_chunk(c + 1, bf ^ 1);
            cpa_commit();
            cpa_wait<1>();   // chunk c complete; c+1 may still be in flight
        } else {
            cpa_wait<0>();   // last chunk: drain everything
        }
        __syncthreads();

        // ---- compute (R1 microkernel; A reads are scalar row-major) ----
#pragma unroll
        for (int kk = 0; kk < BK; ++kk) {
            float a[8], b[8];
#pragma unroll
            for (int i = 0; i < 8; ++i)
                a[i] = sA[bf][ty * 8 + i][kk];
            float4 b0 = *reinterpret_cast<const float4*>(&sB[bf][kk][tx * 8]);
            float4 b1 = *reinterpret_cast<const float4*>(&sB[bf][kk][tx * 8 + 4]);
            b[0]=b0.x; b[1]=b0.y; b[2]=b0.z; b[3]=b0.w;
            b[4]=b1.x; b[5]=b1.y; b[6]=b1.z; b[7]=b1.w;
#pragma unroll
            for (int i = 0; i < 8; ++i)
#pragma unroll
                for (int j = 0; j < 8; ++j)
                    acc[i][j] = fmaf(a[i], b[j], acc[i][j]);
        }
        __syncthreads();
    }

    // ---- epilogue (VERBATIM R1): bias (+ReLU layer0), float4 stores ----
    float bv[8];
#pragma unroll
    for (int j = 0; j < 8; ++j) bv[j] = bias[tx * 8 + j];

    const bool do_relu = (layer == 0);
#pragma unroll
    for (int i = 0; i < 8; ++i) {
        int grow = row0 + ty * 8 + i;
        if (grow < N_NODES) {
            float v[8];
#pragma unroll
            for (int j = 0; j < 8; ++j) {
                float z = acc[i][j] + bv[j];
                v[j] = do_relu ? fmaxf(z, 0.f) : z;
            }
            float* op = outF + (size_t)grow * BN + tx * 8;
            *reinterpret_cast<float4*>(op)     = make_float4(v[0], v[1], v[2], v[3]);
            *reinterpret_cast<float4*>(op + 4) = make_float4(v[4], v[5], v[6], v[7]);
        }
    }
}

// ---------------------------------------------------------------------------
// Launch: gather -> gemm -> gather -> gemm. Graph-capturable, allocation-free.
// ---------------------------------------------------------------------------
extern "C" void kernel_launch(void* const* d_in, const int* in_sizes, int n_in,
                              void* d_out, int out_size) {
    const float* feats = (const float*)d_in[0];
    const int*   nidx  = (const int*)d_in[1];
    const float* Ws    = (const float*)d_in[2];
    const float* bs    = (const float*)d_in[3];
    float* out = (float*)d_out;

    const int gather_blocks = (N_NODES * 32 + 255) / 256;   // 12500
    const int gemm_blocks = (N_NODES + BM - 1) / BM;        // 782

    // Layer 0: agg = mean(feats[idx0]); g_h = relu([feats|agg] @ W0 + b0)
    gather_mean_kernel<<<gather_blocks, 256>>>(feats, nidx);
    sage_gemm_ffma<<<gemm_blocks, 256>>>(feats, Ws, bs, g_h, 0);

    // Layer 1: agg = mean(g_h[idx1]); out = [g_h|agg] @ W1 + b1
    gather_mean_kernel<<<gather_blocks, 256>>>(g_h, nidx + (size_t)N_NODES * K_NEIGH);
    sage_gemm_ffma<<<gemm_blocks, 256>>>(g_h, Ws + 256 * 128, bs + 128, out, 1);
}